// round 13
// baseline (speedup 1.0000x reference)
#include <cuda_runtime.h>
#include <cuda_pipeline.h>
#include <math.h>

#define Bsz 16
#define Ssz 2048
#define NP  (Ssz / 2)            // 1024 step pairs
#define Dsz 256
#define LAM (0.02f / 4096.0f)    // 0.01 * 2/(B*D)
#define TSTR 260                 // smem tile row stride (floats), padded
#define TSZ (Bsz * TSTR)         // one [16 x TSTR] tensor tile (floats)
#define SLOT (2 * TSZ)           // per-step slot {tr, st}

// Scratch (device globals: allocation-free per harness rules)
__device__ float g_state[Ssz * Bsz * Dsz];   // [s][b][k]  = tanh(alpha1*x)
__device__ float g_train[Ssz * Bsz * Dsz];   // [s][b][k]  = state + noise
__device__ float g_M[Ssz * Bsz * Bsz];       // [s][b][j]  = state_s[b]·train_s[j]
__device__ float g_A[NP * Bsz * Bsz];        // [ps][b][j] = train_{s+1}[b]·train_s[j]
__device__ float g_G[NP * Bsz * Bsz];        // [ps][b][j] = state_{s+1}[b]·train_s[j]
__device__ float g_v[Bsz * Ssz * Dsz];       // [b][s][k]  = tanh(alpha2*x)

// ---------------------------------------------------------------------------
// prep: elementwise tanh/add -> state, train (as [s][b][k]) and v
// ---------------------------------------------------------------------------
__global__ void prep_kernel(const float* __restrict__ x, const float* __restrict__ noise,
                            const float* __restrict__ a1, const float* __restrict__ a2) {
    int idx4 = blockIdx.x * blockDim.x + threadIdx.x;
    int base = idx4 * 4;
    int k  = base & (Dsz - 1);
    int bs = base >> 8;
    int b  = bs >> 11;
    int s  = bs & (Ssz - 1);

    float4 xv = ((const float4*)x)[idx4];
    float4 nv = ((const float4*)noise)[idx4];
    float4 A1 = ((const float4*)a1)[k >> 2];
    float4 A2 = ((const float4*)a2)[k >> 2];

    float4 st, tr, vv;
    st.x = tanhf(A1.x * xv.x);  st.y = tanhf(A1.y * xv.y);
    st.z = tanhf(A1.z * xv.z);  st.w = tanhf(A1.w * xv.w);
    tr.x = st.x + nv.x; tr.y = st.y + nv.y; tr.z = st.z + nv.z; tr.w = st.w + nv.w;
    vv.x = tanhf(A2.x * xv.x);  vv.y = tanhf(A2.y * xv.y);
    vv.z = tanhf(A2.z * xv.z);  vv.w = tanhf(A2.w * xv.w);

    int o = (s * Bsz + b) * Dsz + k;
    *(float4*)&g_state[o] = st;
    *(float4*)&g_train[o] = tr;
    ((float4*)g_v)[idx4] = vv;
}

// ---------------------------------------------------------------------------
// prep_pair: per pair ps (s=2ps): M_s, M_{s+1}, A, G  (all 16x16)
// ---------------------------------------------------------------------------
__global__ void prep_pair_kernel() {
    extern __shared__ float sm[];
    float* s_trs = sm;
    float* s_sts = sm + TSZ;
    float* s_tr1 = sm + 2 * TSZ;
    float* s_st1 = sm + 3 * TSZ;

    int ps = blockIdx.x;
    int s  = 2 * ps;
    const float* gt = g_train + (size_t)s * (Bsz * Dsz);
    const float* gs = g_state + (size_t)s * (Bsz * Dsz);
    int tid = threadIdx.x;

#pragma unroll
    for (int i = 0; i < 4; i++) {
        int idx4 = tid + i * 256;
        int b  = idx4 >> 6;
        int kc = (idx4 & 63) << 2;
        int off = b * TSTR + kc;
        *(float4*)&s_trs[off] = *(const float4*)&gt[idx4 * 4];
        *(float4*)&s_sts[off] = *(const float4*)&gs[idx4 * 4];
        *(float4*)&s_tr1[off] = *(const float4*)&gt[Bsz * Dsz + idx4 * 4];
        *(float4*)&s_st1[off] = *(const float4*)&gs[Bsz * Dsz + idx4 * 4];
    }
    __syncthreads();

    int b = tid >> 4;
    int j = tid & 15;
    float mS = 0.f, m1 = 0.f, aa = 0.f, gg = 0.f;
#pragma unroll 4
    for (int k = 0; k < Dsz; k += 4) {
        float4 tsj = *(float4*)&s_trs[j * TSTR + k];
        float4 t1j = *(float4*)&s_tr1[j * TSTR + k];
        float4 ssb = *(float4*)&s_sts[b * TSTR + k];
        float4 s1b = *(float4*)&s_st1[b * TSTR + k];
        float4 t1b = *(float4*)&s_tr1[b * TSTR + k];
        mS += ssb.x * tsj.x + ssb.y * tsj.y + ssb.z * tsj.z + ssb.w * tsj.w;
        m1 += s1b.x * t1j.x + s1b.y * t1j.y + s1b.z * t1j.z + s1b.w * t1j.w;
        aa += t1b.x * tsj.x + t1b.y * tsj.y + t1b.z * tsj.z + t1b.w * tsj.w;
        gg += s1b.x * tsj.x + s1b.y * tsj.y + s1b.z * tsj.z + s1b.w * tsj.w;
    }
    g_M[((size_t)s * Bsz + b) * Bsz + j]       = mS;
    g_M[((size_t)(s + 1) * Bsz + b) * Bsz + j] = m1;
    g_A[((size_t)ps * Bsz + b) * Bsz + j]      = aa;
    g_G[((size_t)ps * Bsz + b) * Bsz + j]      = gg;
}

// ---------------------------------------------------------------------------
// ff: out[row][j] = u(row,j) * sum_k v[row][k] * Wp[j][k]
// ---------------------------------------------------------------------------
__global__ void ff_kernel(const float* __restrict__ Wp,
                          const float* __restrict__ ffa, const float* __restrict__ ffb,
                          const float* __restrict__ ffg, const float* __restrict__ ffe,
                          float* __restrict__ out) {
    __shared__ float As[16][68];
    __shared__ float Bs[16][68];

    int rowTile = blockIdx.x * 64;
    int jTile   = blockIdx.y * 64;
    int tid = threadIdx.x;
    int tx = tid & 15;
    int ty = tid >> 4;

    float acc[4][4];
#pragma unroll
    for (int i = 0; i < 4; i++)
#pragma unroll
        for (int j = 0; j < 4; j++) acc[i][j] = 0.0f;

    int r  = tid >> 2;
    int kk = (tid & 3) * 4;

    for (int kt = 0; kt < Dsz; kt += 16) {
        float4 av = *(const float4*)&g_v[(size_t)(rowTile + r) * Dsz + kt + kk];
        float4 bv = *(const float4*)&Wp[(jTile + r) * Dsz + kt + kk];
        As[kk + 0][r] = av.x; As[kk + 1][r] = av.y; As[kk + 2][r] = av.z; As[kk + 3][r] = av.w;
        Bs[kk + 0][r] = bv.x; Bs[kk + 1][r] = bv.y; Bs[kk + 2][r] = bv.z; Bs[kk + 3][r] = bv.w;
        __syncthreads();
#pragma unroll
        for (int k2 = 0; k2 < 16; k2++) {
            float4 a = *(float4*)&As[k2][ty * 4];
            float4 b = *(float4*)&Bs[k2][tx * 4];
            acc[0][0] += a.x * b.x; acc[0][1] += a.x * b.y; acc[0][2] += a.x * b.z; acc[0][3] += a.x * b.w;
            acc[1][0] += a.y * b.x; acc[1][1] += a.y * b.y; acc[1][2] += a.y * b.z; acc[1][3] += a.y * b.w;
            acc[2][0] += a.z * b.x; acc[2][1] += a.z * b.y; acc[2][2] += a.z * b.z; acc[2][3] += a.z * b.w;
            acc[3][0] += a.w * b.x; acc[3][1] += a.w * b.y; acc[3][2] += a.w * b.z; acc[3][3] += a.w * b.w;
        }
        __syncthreads();
    }

    float gg = ffg[0];
    float ee = ffe[0];
#pragma unroll
    for (int i = 0; i < 4; i++) {
        int row = rowTile + ty * 4 + i;
#pragma unroll
        for (int j = 0; j < 4; j++) {
            int col = jTile + tx * 4 + j;
            float vv = g_v[(size_t)row * Dsz + col];
            float za = ffa[col] * vv;
            float gel = 0.5f * za * (1.0f + erff(za * 0.70710678118654752f));
            float u = gg * gel + ee * sinf(ffb[col] * vv);
            out[(size_t)row * Dsz + col] = u * acc[i][j];
        }
    }
}

// ---------------------------------------------------------------------------
// ttt: grid 256, block 128 — ONE W row per block, 4 warps (k split 4x64),
// TWO blocks co-resident per SM (independent pipelines hide each other's
// stalls). Three per-step {tr,st} smem slots (~99 KB), pair processing with
// M/A/G gram corrections, two barriers per pair (race-free publication).
// ---------------------------------------------------------------------------
__device__ __forceinline__ void stage_step(int s, float* dst, int tid) {
    const float* gt = g_train + (size_t)s * (Bsz * Dsz);
    const float* gs = g_state + (size_t)s * (Bsz * Dsz);
#pragma unroll
    for (int i = 0; i < 8; i++) {
        int idx4 = tid + i * 128;          // 0..1023 float4s per tensor
        int b  = idx4 >> 6;
        int kc = (idx4 & 63) << 2;
        int off = b * TSTR + kc;
        __pipeline_memcpy_async(&dst[off],       &gt[idx4 * 4], 16);
        __pipeline_memcpy_async(&dst[TSZ + off], &gs[idx4 * 4], 16);
    }
    __pipeline_commit();
}

__global__ void __launch_bounds__(128, 2) ttt_kernel(const float* __restrict__ Wt,
                                                     float* __restrict__ out) {
    extern __shared__ float smem[];
    float* sm_slot  = smem;                 // [3][SLOT]
    float* sm_cross = smem + 3 * SLOT;      // [4 warps][2][32]

    int tid  = threadIdx.x;
    int warp = tid >> 5;                    // 0..3
    int lane = tid & 31;
    int d1   = blockIdx.x;                  // W row for this block
    int k0   = warp * 64 + 2 * lane;        // lane's 2 k's

    float2 wv = *(const float2*)&Wt[d1 * Dsz + k0];

    bool rdout = (warp == 0 && lane >= 16);
    int  ob    = lane - 16;
    bool loA   = (lane < 16);

    stage_step(0, sm_slot + 0 * SLOT, tid);
    stage_step(1, sm_slot + 1 * SLOT, tid);
    stage_step(2, sm_slot + 2 * SLOT, tid);

    for (int ps = 0; ps < NP; ps++) {
        int s0 = 2 * ps;
        int s1 = s0 + 1;
        float* b0 = sm_slot + (s0 % 3) * SLOT;   // {tr0 | st0}
        float* b1 = sm_slot + (s1 % 3) * SLOT;   // {tr1 | st1}

        // ---- off-chain gmem prefetches ----
        float4 A0, A1, A2, A3;
        if (loA) {
            const float4* Ar = (const float4*)(g_A + ((size_t)ps * Bsz + lane) * Bsz);
            A0 = Ar[0]; A1 = Ar[1]; A2 = Ar[2]; A3 = Ar[3];
        }
        float4 m0, m1, m2, m3, n0, n1, n2, n3, G0, G1, G2, G3;
        float* op0 = 0; float* op1 = 0; float o0 = 0.f, o1 = 0.f;
        if (rdout) {
            const float4* Mr = (const float4*)(g_M + ((size_t)s0 * Bsz + ob) * Bsz);
            m0 = Mr[0]; m1 = Mr[1]; m2 = Mr[2]; m3 = Mr[3];
            const float4* Nr = (const float4*)(g_M + ((size_t)s1 * Bsz + ob) * Bsz);
            n0 = Nr[0]; n1 = Nr[1]; n2 = Nr[2]; n3 = Nr[3];
            const float4* Gr = (const float4*)(g_G + ((size_t)ps * Bsz + ob) * Bsz);
            G0 = Gr[0]; G1 = Gr[1]; G2 = Gr[2]; G3 = Gr[3];
            op0 = out + ((size_t)ob * Ssz + s0) * Dsz + d1;
            op1 = op0 + Dsz;
            o0 = *op0; o1 = *op1;
        }

        // ---- wait for this pair's slots, then PUBLISH across threads ----
        if (ps + 1 < NP) { __pipeline_wait_prior(1); }
        else             { __pipeline_wait_prior(0); }
        __syncthreads();

        // ---- phase 1: partial dots for BOTH steps against w0 ----
        float a[32], c[32];
        float2 tc0[16], tc1[16];
#pragma unroll
        for (int b = 0; b < 16; b++) {
            float2 t0 = *(const float2*)&b0[b * TSTR + k0];
            float2 s0v = *(const float2*)&b0[TSZ + b * TSTR + k0];
            float2 t1 = *(const float2*)&b1[b * TSTR + k0];
            float2 s1v = *(const float2*)&b1[TSZ + b * TSTR + k0];
            tc0[b] = t0;
            tc1[b] = t1;
            a[b]      = t0.x * wv.x + t0.y * wv.y;    // p1 partial
            a[16 + b] = s0v.x * wv.x + s0v.y * wv.y;  // q1 partial
            c[b]      = t1.x * wv.x + t1.y * wv.y;    // p2_0 partial
            c[16 + b] = s1v.x * wv.x + s1v.y * wv.y;  // q2_0 partial
        }
        float stc0 = 0.f, stc1 = 0.f;
        if (loA) {
            stc0 = b0[TSZ + lane * TSTR + d1];
            stc1 = b1[TSZ + lane * TSTR + d1];
        }

        // ---- interleaved register butterfly ----
#pragma unroll
        for (int m = 16; m >= 1; m >>= 1) {
            bool up = (lane & m) != 0;
#pragma unroll
            for (int j = 0; j < m; j++) {
                float ka = up ? a[j + m] : a[j];
                float ga = up ? a[j]     : a[j + m];
                a[j] = ka + __shfl_xor_sync(0xffffffffu, ga, m);
                float kc = up ? c[j + m] : c[j];
                float gc = up ? c[j]     : c[j + m];
                c[j] = kc + __shfl_xor_sync(0xffffffffu, gc, m);
            }
        }

        // ---- cross-warp combine: write, barrier, (stage next), read ----
        sm_cross[(warp * 2 + 0) * 32 + lane] = a[0];
        sm_cross[(warp * 2 + 1) * 32 + lane] = c[0];
        __syncthreads();

        // Stage steps s0+3 and s0+4 — their target slots' readers are all
        // past the barrier above (slot reads happen only in phase-1).
        if (s0 + 3 < Ssz) stage_step(s0 + 3, sm_slot + ((s0 + 3) % 3) * SLOT, tid);
        if (s0 + 4 < Ssz) stage_step(s0 + 4, sm_slot + ((s0 + 4) % 3) * SLOT, tid);

        float tot_a = (sm_cross[0 * 32 + lane] + sm_cross[2 * 32 + lane])
                    + (sm_cross[4 * 32 + lane] + sm_cross[6 * 32 + lane]);
        float tot_c = (sm_cross[1 * 32 + lane] + sm_cross[3 * 32 + lane])
                    + (sm_cross[5 * 32 + lane] + sm_cross[7 * 32 + lane]);

        // ---- step s0: dif1 on lanes<16 ----
        float dv1 = loA ? (tot_a - stc0) : 0.f;
        float dif1[16];
#pragma unroll
        for (int j = 0; j < 16; j++) dif1[j] = __shfl_sync(0xffffffffu, dv1, j);

        if (rdout) {
            float ch = m0.x * dif1[0]  + m0.y * dif1[1]  + m0.z * dif1[2]  + m0.w * dif1[3]
                     + m1.x * dif1[4]  + m1.y * dif1[5]  + m1.z * dif1[6]  + m1.w * dif1[7];
            float cl = m2.x * dif1[8]  + m2.y * dif1[9]  + m2.z * dif1[10] + m2.w * dif1[11]
                     + m3.x * dif1[12] + m3.y * dif1[13] + m3.z * dif1[14] + m3.w * dif1[15];
            *op0 = o0 + tot_a - LAM * (ch + cl);
        }

        // ---- step s1: correct p2 with A·dif1, form dif2 ----
        float dv2 = 0.f;
        if (loA) {
            float cAh = A0.x * dif1[0]  + A0.y * dif1[1]  + A0.z * dif1[2]  + A0.w * dif1[3]
                      + A1.x * dif1[4]  + A1.y * dif1[5]  + A1.z * dif1[6]  + A1.w * dif1[7];
            float cAl = A2.x * dif1[8]  + A2.y * dif1[9]  + A2.z * dif1[10] + A2.w * dif1[11]
                      + A3.x * dif1[12] + A3.y * dif1[13] + A3.z * dif1[14] + A3.w * dif1[15];
            dv2 = (tot_c - LAM * (cAh + cAl)) - stc1;
        }
        float dif2[16];
#pragma unroll
        for (int j = 0; j < 16; j++) dif2[j] = __shfl_sync(0xffffffffu, dv2, j);

        if (rdout) {
            float gh = G0.x * dif1[0]  + G0.y * dif1[1]  + G0.z * dif1[2]  + G0.w * dif1[3]
                     + G1.x * dif1[4]  + G1.y * dif1[5]  + G1.z * dif1[6]  + G1.w * dif1[7];
            float gl = G2.x * dif1[8]  + G2.y * dif1[9]  + G2.z * dif1[10] + G2.w * dif1[11]
                     + G3.x * dif1[12] + G3.y * dif1[13] + G3.z * dif1[14] + G3.w * dif1[15];
            float q2 = tot_c - LAM * (gh + gl);
            float nh = n0.x * dif2[0]  + n0.y * dif2[1]  + n0.z * dif2[2]  + n0.w * dif2[3]
                     + n1.x * dif2[4]  + n1.y * dif2[5]  + n1.z * dif2[6]  + n1.w * dif2[7];
            float nl = n2.x * dif2[8]  + n2.y * dif2[9]  + n2.z * dif2[10] + n2.w * dif2[11]
                     + n3.x * dif2[12] + n3.y * dif2[13] + n3.z * dif2[14] + n3.w * dif2[15];
            *op1 = o1 + q2 - LAM * (nh + nl);
        }

        // ---- combined w update, 2-way split accumulators ----
        float dwx0 = 0.f, dwx1 = 0.f, dwy0 = 0.f, dwy1 = 0.f;
#pragma unroll
        for (int b = 0; b < 16; b += 2) {
            dwx0 += dif1[b]     * tc0[b].x     + dif2[b]     * tc1[b].x;
            dwy0 += dif1[b]     * tc0[b].y     + dif2[b]     * tc1[b].y;
            dwx1 += dif1[b + 1] * tc0[b + 1].x + dif2[b + 1] * tc1[b + 1].x;
            dwy1 += dif1[b + 1] * tc0[b + 1].y + dif2[b + 1] * tc1[b + 1].y;
        }
        wv.x -= LAM * (dwx0 + dwx1);
        wv.y -= LAM * (dwy0 + dwy1);
    }
}

// ---------------------------------------------------------------------------
extern "C" void kernel_launch(void* const* d_in, const int* in_sizes, int n_in,
                              void* d_out, int out_size) {
    const float* x     = (const float*)d_in[0];
    const float* noise = (const float*)d_in[1];
    const float* a1    = (const float*)d_in[2];
    const float* a2    = (const float*)d_in[3];
    const float* Wt    = (const float*)d_in[4];
    const float* Wp    = (const float*)d_in[5];
    const float* ffa   = (const float*)d_in[6];
    const float* ffb   = (const float*)d_in[7];
    const float* ffg   = (const float*)d_in[8];
    const float* ffe   = (const float*)d_in[9];
    float* out = (float*)d_out;

    prep_kernel<<<(Bsz * Ssz * Dsz / 4) / 256, 256>>>(x, noise, a1, a2);

    const int PREP_SMEM = 4 * TSZ * (int)sizeof(float);               // ~66.6 KB
    cudaFuncSetAttribute(prep_pair_kernel, cudaFuncAttributeMaxDynamicSharedMemorySize, PREP_SMEM);
    prep_pair_kernel<<<NP, 256, PREP_SMEM>>>();

    ff_kernel<<<dim3((Bsz * Ssz) / 64, Dsz / 64), 256>>>(Wp, ffa, ffb, ffg, ffe, out);

    const int TTT_SMEM = (3 * SLOT + 4 * 2 * 32) * (int)sizeof(float);  // ~98.8 KB
    cudaFuncSetAttribute(ttt_kernel, cudaFuncAttributeMaxDynamicSharedMemorySize, TTT_SMEM);
    ttt_kernel<<<Dsz, 128, TTT_SMEM>>>(Wt, out);
}

// round 15
// speedup vs baseline: 1.0038x; 1.0038x over previous
#include <cuda_runtime.h>
#include <cuda_pipeline.h>
#include <math.h>

#define Bsz 16
#define Ssz 2048
#define NP  (Ssz / 2)            // 1024 step pairs
#define Dsz 256
#define LAM (0.02f / 4096.0f)    // 0.01 * 2/(B*D)
#define TSTR 260                 // smem tile row stride (floats), padded
#define TSZ (Bsz * TSTR)         // one [16 x TSTR] tensor tile (floats)
#define SLOT (2 * TSZ)           // per-step slot {tr, st}

// Scratch (device globals: allocation-free per harness rules)
__device__ float g_state[Ssz * Bsz * Dsz];   // [s][b][k]  = tanh(alpha1*x)
__device__ float g_train[Ssz * Bsz * Dsz];   // [s][b][k]  = state + noise
__device__ float g_M[Ssz * Bsz * Bsz];       // [s][b][j]  = state_s[b]·train_s[j]
__device__ float g_A[NP * Bsz * Bsz];        // [ps][b][j] = train_{s+1}[b]·train_s[j]
__device__ float g_G[NP * Bsz * Bsz];        // [ps][b][j] = state_{s+1}[b]·train_s[j]
__device__ float g_v[Bsz * Ssz * Dsz];       // [b][s][k]  = tanh(alpha2*x)

// ---------------------------------------------------------------------------
// prep: elementwise tanh/add -> state, train (as [s][b][k]) and v
// ---------------------------------------------------------------------------
__global__ void prep_kernel(const float* __restrict__ x, const float* __restrict__ noise,
                            const float* __restrict__ a1, const float* __restrict__ a2) {
    int idx4 = blockIdx.x * blockDim.x + threadIdx.x;
    int base = idx4 * 4;
    int k  = base & (Dsz - 1);
    int bs = base >> 8;
    int b  = bs >> 11;
    int s  = bs & (Ssz - 1);

    float4 xv = ((const float4*)x)[idx4];
    float4 nv = ((const float4*)noise)[idx4];
    float4 A1 = ((const float4*)a1)[k >> 2];
    float4 A2 = ((const float4*)a2)[k >> 2];

    float4 st, tr, vv;
    st.x = tanhf(A1.x * xv.x);  st.y = tanhf(A1.y * xv.y);
    st.z = tanhf(A1.z * xv.z);  st.w = tanhf(A1.w * xv.w);
    tr.x = st.x + nv.x; tr.y = st.y + nv.y; tr.z = st.z + nv.z; tr.w = st.w + nv.w;
    vv.x = tanhf(A2.x * xv.x);  vv.y = tanhf(A2.y * xv.y);
    vv.z = tanhf(A2.z * xv.z);  vv.w = tanhf(A2.w * xv.w);

    int o = (s * Bsz + b) * Dsz + k;
    *(float4*)&g_state[o] = st;
    *(float4*)&g_train[o] = tr;
    ((float4*)g_v)[idx4] = vv;
}

// ---------------------------------------------------------------------------
// prep_pair: per pair ps (s=2ps): M_s, M_{s+1}, A, G  (all 16x16)
// ---------------------------------------------------------------------------
__global__ void prep_pair_kernel() {
    extern __shared__ float sm[];
    float* s_trs = sm;
    float* s_sts = sm + TSZ;
    float* s_tr1 = sm + 2 * TSZ;
    float* s_st1 = sm + 3 * TSZ;

    int ps = blockIdx.x;
    int s  = 2 * ps;
    const float* gt = g_train + (size_t)s * (Bsz * Dsz);
    const float* gs = g_state + (size_t)s * (Bsz * Dsz);
    int tid = threadIdx.x;

#pragma unroll
    for (int i = 0; i < 4; i++) {
        int idx4 = tid + i * 256;
        int b  = idx4 >> 6;
        int kc = (idx4 & 63) << 2;
        int off = b * TSTR + kc;
        *(float4*)&s_trs[off] = *(const float4*)&gt[idx4 * 4];
        *(float4*)&s_sts[off] = *(const float4*)&gs[idx4 * 4];
        *(float4*)&s_tr1[off] = *(const float4*)&gt[Bsz * Dsz + idx4 * 4];
        *(float4*)&s_st1[off] = *(const float4*)&gs[Bsz * Dsz + idx4 * 4];
    }
    __syncthreads();

    int b = tid >> 4;
    int j = tid & 15;
    float mS = 0.f, m1 = 0.f, aa = 0.f, gg = 0.f;
#pragma unroll 4
    for (int k = 0; k < Dsz; k += 4) {
        float4 tsj = *(float4*)&s_trs[j * TSTR + k];
        float4 t1j = *(float4*)&s_tr1[j * TSTR + k];
        float4 ssb = *(float4*)&s_sts[b * TSTR + k];
        float4 s1b = *(float4*)&s_st1[b * TSTR + k];
        float4 t1b = *(float4*)&s_tr1[b * TSTR + k];
        mS += ssb.x * tsj.x + ssb.y * tsj.y + ssb.z * tsj.z + ssb.w * tsj.w;
        m1 += s1b.x * t1j.x + s1b.y * t1j.y + s1b.z * t1j.z + s1b.w * t1j.w;
        aa += t1b.x * tsj.x + t1b.y * tsj.y + t1b.z * tsj.z + t1b.w * tsj.w;
        gg += s1b.x * tsj.x + s1b.y * tsj.y + s1b.z * tsj.z + s1b.w * tsj.w;
    }
    g_M[((size_t)s * Bsz + b) * Bsz + j]       = mS;
    g_M[((size_t)(s + 1) * Bsz + b) * Bsz + j] = m1;
    g_A[((size_t)ps * Bsz + b) * Bsz + j]      = aa;
    g_G[((size_t)ps * Bsz + b) * Bsz + j]      = gg;
}

// ---------------------------------------------------------------------------
// ff: out[row][j] = u(row,j) * sum_k v[row][k] * Wp[j][k]
// ---------------------------------------------------------------------------
__global__ void ff_kernel(const float* __restrict__ Wp,
                          const float* __restrict__ ffa, const float* __restrict__ ffb,
                          const float* __restrict__ ffg, const float* __restrict__ ffe,
                          float* __restrict__ out) {
    __shared__ float As[16][68];
    __shared__ float Bs[16][68];

    int rowTile = blockIdx.x * 64;
    int jTile   = blockIdx.y * 64;
    int tid = threadIdx.x;
    int tx = tid & 15;
    int ty = tid >> 4;

    float acc[4][4];
#pragma unroll
    for (int i = 0; i < 4; i++)
#pragma unroll
        for (int j = 0; j < 4; j++) acc[i][j] = 0.0f;

    int r  = tid >> 2;
    int kk = (tid & 3) * 4;

    for (int kt = 0; kt < Dsz; kt += 16) {
        float4 av = *(const float4*)&g_v[(size_t)(rowTile + r) * Dsz + kt + kk];
        float4 bv = *(const float4*)&Wp[(jTile + r) * Dsz + kt + kk];
        As[kk + 0][r] = av.x; As[kk + 1][r] = av.y; As[kk + 2][r] = av.z; As[kk + 3][r] = av.w;
        Bs[kk + 0][r] = bv.x; Bs[kk + 1][r] = bv.y; Bs[kk + 2][r] = bv.z; Bs[kk + 3][r] = bv.w;
        __syncthreads();
#pragma unroll
        for (int k2 = 0; k2 < 16; k2++) {
            float4 a = *(float4*)&As[k2][ty * 4];
            float4 b = *(float4*)&Bs[k2][tx * 4];
            acc[0][0] += a.x * b.x; acc[0][1] += a.x * b.y; acc[0][2] += a.x * b.z; acc[0][3] += a.x * b.w;
            acc[1][0] += a.y * b.x; acc[1][1] += a.y * b.y; acc[1][2] += a.y * b.z; acc[1][3] += a.y * b.w;
            acc[2][0] += a.z * b.x; acc[2][1] += a.z * b.y; acc[2][2] += a.z * b.z; acc[2][3] += a.z * b.w;
            acc[3][0] += a.w * b.x; acc[3][1] += a.w * b.y; acc[3][2] += a.w * b.z; acc[3][3] += a.w * b.w;
        }
        __syncthreads();
    }

    float gg = ffg[0];
    float ee = ffe[0];
#pragma unroll
    for (int i = 0; i < 4; i++) {
        int row = rowTile + ty * 4 + i;
#pragma unroll
        for (int j = 0; j < 4; j++) {
            int col = jTile + tx * 4 + j;
            float vv = g_v[(size_t)row * Dsz + col];
            float za = ffa[col] * vv;
            float gel = 0.5f * za * (1.0f + erff(za * 0.70710678118654752f));
            float u = gg * gel + ee * sinf(ffb[col] * vv);
            out[(size_t)row * Dsz + col] = u * acc[i][j];
        }
    }
}

// ---------------------------------------------------------------------------
// ttt: grid 256, block 128 — ONE W row per block, 4 warps (k split 4x64),
// TWO blocks co-resident per SM (independent pipelines hide each other's
// stalls). Three per-step {tr,st} smem slots (~99 KB), pair processing with
// M/A/G gram corrections, two barriers per pair (race-free publication).
// ---------------------------------------------------------------------------
__device__ __forceinline__ void stage_step(int s, float* dst, int tid) {
    const float* gt = g_train + (size_t)s * (Bsz * Dsz);
    const float* gs = g_state + (size_t)s * (Bsz * Dsz);
#pragma unroll
    for (int i = 0; i < 8; i++) {
        int idx4 = tid + i * 128;          // 0..1023 float4s per tensor
        int b  = idx4 >> 6;
        int kc = (idx4 & 63) << 2;
        int off = b * TSTR + kc;
        __pipeline_memcpy_async(&dst[off],       &gt[idx4 * 4], 16);
        __pipeline_memcpy_async(&dst[TSZ + off], &gs[idx4 * 4], 16);
    }
    __pipeline_commit();
}

__global__ void __launch_bounds__(128, 2) ttt_kernel(const float* __restrict__ Wt,
                                                     float* __restrict__ out) {
    extern __shared__ float smem[];
    float* sm_slot  = smem;                 // [3][SLOT]
    float* sm_cross = smem + 3 * SLOT;      // [4 warps][2][32]

    int tid  = threadIdx.x;
    int warp = tid >> 5;                    // 0..3
    int lane = tid & 31;
    int d1   = blockIdx.x;                  // W row for this block
    int k0   = warp * 64 + 2 * lane;        // lane's 2 k's

    float2 wv = *(const float2*)&Wt[d1 * Dsz + k0];

    bool rdout = (warp == 0 && lane >= 16);
    int  ob    = lane - 16;
    bool loA   = (lane < 16);

    stage_step(0, sm_slot + 0 * SLOT, tid);
    stage_step(1, sm_slot + 1 * SLOT, tid);
    stage_step(2, sm_slot + 2 * SLOT, tid);

    for (int ps = 0; ps < NP; ps++) {
        int s0 = 2 * ps;
        int s1 = s0 + 1;
        float* b0 = sm_slot + (s0 % 3) * SLOT;   // {tr0 | st0}
        float* b1 = sm_slot + (s1 % 3) * SLOT;   // {tr1 | st1}

        // ---- off-chain gmem prefetches ----
        float4 A0, A1, A2, A3;
        if (loA) {
            const float4* Ar = (const float4*)(g_A + ((size_t)ps * Bsz + lane) * Bsz);
            A0 = Ar[0]; A1 = Ar[1]; A2 = Ar[2]; A3 = Ar[3];
        }
        float4 m0, m1, m2, m3, n0, n1, n2, n3, G0, G1, G2, G3;
        float* op0 = 0; float* op1 = 0; float o0 = 0.f, o1 = 0.f;
        if (rdout) {
            const float4* Mr = (const float4*)(g_M + ((size_t)s0 * Bsz + ob) * Bsz);
            m0 = Mr[0]; m1 = Mr[1]; m2 = Mr[2]; m3 = Mr[3];
            const float4* Nr = (const float4*)(g_M + ((size_t)s1 * Bsz + ob) * Bsz);
            n0 = Nr[0]; n1 = Nr[1]; n2 = Nr[2]; n3 = Nr[3];
            const float4* Gr = (const float4*)(g_G + ((size_t)ps * Bsz + ob) * Bsz);
            G0 = Gr[0]; G1 = Gr[1]; G2 = Gr[2]; G3 = Gr[3];
            op0 = out + ((size_t)ob * Ssz + s0) * Dsz + d1;
            op1 = op0 + Dsz;
            o0 = *op0; o1 = *op1;
        }

        // ---- wait for this pair's slots, then PUBLISH across threads ----
        if (ps + 1 < NP) { __pipeline_wait_prior(1); }
        else             { __pipeline_wait_prior(0); }
        __syncthreads();

        // ---- phase 1: partial dots for BOTH steps against w0 ----
        float a[32], c[32];
        float2 tc0[16], tc1[16];
#pragma unroll
        for (int b = 0; b < 16; b++) {
            float2 t0 = *(const float2*)&b0[b * TSTR + k0];
            float2 s0v = *(const float2*)&b0[TSZ + b * TSTR + k0];
            float2 t1 = *(const float2*)&b1[b * TSTR + k0];
            float2 s1v = *(const float2*)&b1[TSZ + b * TSTR + k0];
            tc0[b] = t0;
            tc1[b] = t1;
            a[b]      = t0.x * wv.x + t0.y * wv.y;    // p1 partial
            a[16 + b] = s0v.x * wv.x + s0v.y * wv.y;  // q1 partial
            c[b]      = t1.x * wv.x + t1.y * wv.y;    // p2_0 partial
            c[16 + b] = s1v.x * wv.x + s1v.y * wv.y;  // q2_0 partial
        }
        float stc0 = 0.f, stc1 = 0.f;
        if (loA) {
            stc0 = b0[TSZ + lane * TSTR + d1];
            stc1 = b1[TSZ + lane * TSTR + d1];
        }

        // ---- interleaved register butterfly ----
#pragma unroll
        for (int m = 16; m >= 1; m >>= 1) {
            bool up = (lane & m) != 0;
#pragma unroll
            for (int j = 0; j < m; j++) {
                float ka = up ? a[j + m] : a[j];
                float ga = up ? a[j]     : a[j + m];
                a[j] = ka + __shfl_xor_sync(0xffffffffu, ga, m);
                float kc = up ? c[j + m] : c[j];
                float gc = up ? c[j]     : c[j + m];
                c[j] = kc + __shfl_xor_sync(0xffffffffu, gc, m);
            }
        }

        // ---- cross-warp combine: write, barrier, (stage next), read ----
        sm_cross[(warp * 2 + 0) * 32 + lane] = a[0];
        sm_cross[(warp * 2 + 1) * 32 + lane] = c[0];
        __syncthreads();

        // Stage steps s0+3 and s0+4 — their target slots' readers are all
        // past the barrier above (slot reads happen only in phase-1).
        if (s0 + 3 < Ssz) stage_step(s0 + 3, sm_slot + ((s0 + 3) % 3) * SLOT, tid);
        if (s0 + 4 < Ssz) stage_step(s0 + 4, sm_slot + ((s0 + 4) % 3) * SLOT, tid);

        float tot_a = (sm_cross[0 * 32 + lane] + sm_cross[2 * 32 + lane])
                    + (sm_cross[4 * 32 + lane] + sm_cross[6 * 32 + lane]);
        float tot_c = (sm_cross[1 * 32 + lane] + sm_cross[3 * 32 + lane])
                    + (sm_cross[5 * 32 + lane] + sm_cross[7 * 32 + lane]);

        // ---- step s0: dif1 on lanes<16 ----
        float dv1 = loA ? (tot_a - stc0) : 0.f;
        float dif1[16];
#pragma unroll
        for (int j = 0; j < 16; j++) dif1[j] = __shfl_sync(0xffffffffu, dv1, j);

        if (rdout) {
            float ch = m0.x * dif1[0]  + m0.y * dif1[1]  + m0.z * dif1[2]  + m0.w * dif1[3]
                     + m1.x * dif1[4]  + m1.y * dif1[5]  + m1.z * dif1[6]  + m1.w * dif1[7];
            float cl = m2.x * dif1[8]  + m2.y * dif1[9]  + m2.z * dif1[10] + m2.w * dif1[11]
                     + m3.x * dif1[12] + m3.y * dif1[13] + m3.z * dif1[14] + m3.w * dif1[15];
            *op0 = o0 + tot_a - LAM * (ch + cl);
        }

        // ---- step s1: correct p2 with A·dif1, form dif2 ----
        float dv2 = 0.f;
        if (loA) {
            float cAh = A0.x * dif1[0]  + A0.y * dif1[1]  + A0.z * dif1[2]  + A0.w * dif1[3]
                      + A1.x * dif1[4]  + A1.y * dif1[5]  + A1.z * dif1[6]  + A1.w * dif1[7];
            float cAl = A2.x * dif1[8]  + A2.y * dif1[9]  + A2.z * dif1[10] + A2.w * dif1[11]
                      + A3.x * dif1[12] + A3.y * dif1[13] + A3.z * dif1[14] + A3.w * dif1[15];
            dv2 = (tot_c - LAM * (cAh + cAl)) - stc1;
        }
        float dif2[16];
#pragma unroll
        for (int j = 0; j < 16; j++) dif2[j] = __shfl_sync(0xffffffffu, dv2, j);

        if (rdout) {
            float gh = G0.x * dif1[0]  + G0.y * dif1[1]  + G0.z * dif1[2]  + G0.w * dif1[3]
                     + G1.x * dif1[4]  + G1.y * dif1[5]  + G1.z * dif1[6]  + G1.w * dif1[7];
            float gl = G2.x * dif1[8]  + G2.y * dif1[9]  + G2.z * dif1[10] + G2.w * dif1[11]
                     + G3.x * dif1[12] + G3.y * dif1[13] + G3.z * dif1[14] + G3.w * dif1[15];
            float q2 = tot_c - LAM * (gh + gl);
            float nh = n0.x * dif2[0]  + n0.y * dif2[1]  + n0.z * dif2[2]  + n0.w * dif2[3]
                     + n1.x * dif2[4]  + n1.y * dif2[5]  + n1.z * dif2[6]  + n1.w * dif2[7];
            float nl = n2.x * dif2[8]  + n2.y * dif2[9]  + n2.z * dif2[10] + n2.w * dif2[11]
                     + n3.x * dif2[12] + n3.y * dif2[13] + n3.z * dif2[14] + n3.w * dif2[15];
            *op1 = o1 + q2 - LAM * (nh + nl);
        }

        // ---- combined w update, 2-way split accumulators ----
        float dwx0 = 0.f, dwx1 = 0.f, dwy0 = 0.f, dwy1 = 0.f;
#pragma unroll
        for (int b = 0; b < 16; b += 2) {
            dwx0 += dif1[b]     * tc0[b].x     + dif2[b]     * tc1[b].x;
            dwy0 += dif1[b]     * tc0[b].y     + dif2[b]     * tc1[b].y;
            dwx1 += dif1[b + 1] * tc0[b + 1].x + dif2[b + 1] * tc1[b + 1].x;
            dwy1 += dif1[b + 1] * tc0[b + 1].y + dif2[b + 1] * tc1[b + 1].y;
        }
        wv.x -= LAM * (dwx0 + dwx1);
        wv.y -= LAM * (dwy0 + dwy1);
    }
}

// ---------------------------------------------------------------------------
extern "C" void kernel_launch(void* const* d_in, const int* in_sizes, int n_in,
                              void* d_out, int out_size) {
    const float* x     = (const float*)d_in[0];
    const float* noise = (const float*)d_in[1];
    const float* a1    = (const float*)d_in[2];
    const float* a2    = (const float*)d_in[3];
    const float* Wt    = (const float*)d_in[4];
    const float* Wp    = (const float*)d_in[5];
    const float* ffa   = (const float*)d_in[6];
    const float* ffb   = (const float*)d_in[7];
    const float* ffg   = (const float*)d_in[8];
    const float* ffe   = (const float*)d_in[9];
    float* out = (float*)d_out;

    prep_kernel<<<(Bsz * Ssz * Dsz / 4) / 256, 256>>>(x, noise, a1, a2);

    const int PREP_SMEM = 4 * TSZ * (int)sizeof(float);               // ~66.6 KB
    cudaFuncSetAttribute(prep_pair_kernel, cudaFuncAttributeMaxDynamicSharedMemorySize, PREP_SMEM);
    prep_pair_kernel<<<NP, 256, PREP_SMEM>>>();

    ff_kernel<<<dim3((Bsz * Ssz) / 64, Dsz / 64), 256>>>(Wp, ffa, ffb, ffg, ffe, out);

    const int TTT_SMEM = (3 * SLOT + 4 * 2 * 32) * (int)sizeof(float);  // ~98.8 KB
    cudaFuncSetAttribute(ttt_kernel, cudaFuncAttributeMaxDynamicSharedMemorySize, TTT_SMEM);
    ttt_kernel<<<Dsz, 128, TTT_SMEM>>>(Wt, out);
}

// round 17
// speedup vs baseline: 1.3801x; 1.3749x over previous
#include <cuda_runtime.h>
#include <cuda_pipeline.h>
#include <math.h>

#define Bsz 16
#define Ssz 2048
#define NP  (Ssz / 2)            // 1024 step pairs
#define Dsz 256
#define LAM (0.02f / 4096.0f)    // 0.01 * 2/(B*D)
#define TSTR 260                 // smem tile row stride (floats), padded
#define TSZ (Bsz * TSTR)         // one [16 x TSTR] tensor tile (floats)

#define NTTT 128                 // ttt blocks (2 W-rows each)
#define NFFX 512                 // ff row tiles (32768/64)
#define NFFY 4                   // ff col tiles (256/64)

// Scratch (device globals: allocation-free per harness rules)
__device__ float g_state[Ssz * Bsz * Dsz];   // [s][b][k]  = tanh(alpha1*x)
__device__ float g_train[Ssz * Bsz * Dsz];   // [s][b][k]  = state + noise
__device__ float g_M[Ssz * Bsz * Bsz];       // [s][b][j]  = state_s[b]·train_s[j]
__device__ float g_A[NP * Bsz * Bsz];        // [ps][b][j] = train_{s+1}[b]·train_s[j]
__device__ float g_G[NP * Bsz * Bsz];        // [ps][b][j] = state_{s+1}[b]·train_s[j]
__device__ float g_v[Bsz * Ssz * Dsz];       // [b][s][k]  = tanh(alpha2*x)

// ---------------------------------------------------------------------------
// prep: elementwise tanh/add -> state, train (as [s][b][k]) and v
// ---------------------------------------------------------------------------
__global__ void prep_kernel(const float* __restrict__ x, const float* __restrict__ noise,
                            const float* __restrict__ a1, const float* __restrict__ a2) {
    int idx4 = blockIdx.x * blockDim.x + threadIdx.x;
    int base = idx4 * 4;
    int k  = base & (Dsz - 1);
    int bs = base >> 8;
    int b  = bs >> 11;
    int s  = bs & (Ssz - 1);

    float4 xv = ((const float4*)x)[idx4];
    float4 nv = ((const float4*)noise)[idx4];
    float4 A1 = ((const float4*)a1)[k >> 2];
    float4 A2 = ((const float4*)a2)[k >> 2];

    float4 st, tr, vv;
    st.x = tanhf(A1.x * xv.x);  st.y = tanhf(A1.y * xv.y);
    st.z = tanhf(A1.z * xv.z);  st.w = tanhf(A1.w * xv.w);
    tr.x = st.x + nv.x; tr.y = st.y + nv.y; tr.z = st.z + nv.z; tr.w = st.w + nv.w;
    vv.x = tanhf(A2.x * xv.x);  vv.y = tanhf(A2.y * xv.y);
    vv.z = tanhf(A2.z * xv.z);  vv.w = tanhf(A2.w * xv.w);

    int o = (s * Bsz + b) * Dsz + k;
    *(float4*)&g_state[o] = st;
    *(float4*)&g_train[o] = tr;
    ((float4*)g_v)[idx4] = vv;
}

// ---------------------------------------------------------------------------
// prep_pair: per pair ps (s=2ps): M_s, M_{s+1}, A, G  (all 16x16)
// ---------------------------------------------------------------------------
__global__ void prep_pair_kernel() {
    extern __shared__ float sm[];
    float* s_trs = sm;
    float* s_sts = sm + TSZ;
    float* s_tr1 = sm + 2 * TSZ;
    float* s_st1 = sm + 3 * TSZ;

    int ps = blockIdx.x;
    int s  = 2 * ps;
    const float* gt = g_train + (size_t)s * (Bsz * Dsz);
    const float* gs = g_state + (size_t)s * (Bsz * Dsz);
    int tid = threadIdx.x;

#pragma unroll
    for (int i = 0; i < 4; i++) {
        int idx4 = tid + i * 256;
        int b  = idx4 >> 6;
        int kc = (idx4 & 63) << 2;
        int off = b * TSTR + kc;
        *(float4*)&s_trs[off] = *(const float4*)&gt[idx4 * 4];
        *(float4*)&s_sts[off] = *(const float4*)&gs[idx4 * 4];
        *(float4*)&s_tr1[off] = *(const float4*)&gt[Bsz * Dsz + idx4 * 4];
        *(float4*)&s_st1[off] = *(const float4*)&gs[Bsz * Dsz + idx4 * 4];
    }
    __syncthreads();

    int b = tid >> 4;
    int j = tid & 15;
    float mS = 0.f, m1 = 0.f, aa = 0.f, gg = 0.f;
#pragma unroll 4
    for (int k = 0; k < Dsz; k += 4) {
        float4 tsj = *(float4*)&s_trs[j * TSTR + k];
        float4 t1j = *(float4*)&s_tr1[j * TSTR + k];
        float4 ssb = *(float4*)&s_sts[b * TSTR + k];
        float4 s1b = *(float4*)&s_st1[b * TSTR + k];
        float4 t1b = *(float4*)&s_tr1[b * TSTR + k];
        mS += ssb.x * tsj.x + ssb.y * tsj.y + ssb.z * tsj.z + ssb.w * tsj.w;
        m1 += s1b.x * t1j.x + s1b.y * t1j.y + s1b.z * t1j.z + s1b.w * t1j.w;
        aa += t1b.x * tsj.x + t1b.y * tsj.y + t1b.z * tsj.z + t1b.w * tsj.w;
        gg += s1b.x * tsj.x + s1b.y * tsj.y + s1b.z * tsj.z + s1b.w * tsj.w;
    }
    g_M[((size_t)s * Bsz + b) * Bsz + j]       = mS;
    g_M[((size_t)(s + 1) * Bsz + b) * Bsz + j] = m1;
    g_A[((size_t)ps * Bsz + b) * Bsz + j]      = aa;
    g_G[((size_t)ps * Bsz + b) * Bsz + j]      = gg;
}

// ---------------------------------------------------------------------------
// ff role (inside mega kernel): atomicAdd u * (v @ Wp^T) into out
// ---------------------------------------------------------------------------
__device__ void ff_role(float* smem, int t,
                        const float* __restrict__ Wp,
                        const float* __restrict__ ffa, const float* __restrict__ ffb,
                        const float* __restrict__ ffg, const float* __restrict__ ffe,
                        float* __restrict__ out) {
    float* As = smem;              // [16][68]
    float* Bs = smem + 16 * 68;    // [16][68]

    int rowTile = (t % NFFX) * 64;
    int jTile   = (t / NFFX) * 64;
    int tid = threadIdx.x;
    int tx = tid & 15;
    int ty = tid >> 4;

    float acc[4][4];
#pragma unroll
    for (int i = 0; i < 4; i++)
#pragma unroll
        for (int j = 0; j < 4; j++) acc[i][j] = 0.0f;

    int r  = tid >> 2;
    int kk = (tid & 3) * 4;

    for (int kt = 0; kt < Dsz; kt += 16) {
        float4 av = *(const float4*)&g_v[(size_t)(rowTile + r) * Dsz + kt + kk];
        float4 bv = *(const float4*)&Wp[(jTile + r) * Dsz + kt + kk];
        As[(kk + 0) * 68 + r] = av.x; As[(kk + 1) * 68 + r] = av.y;
        As[(kk + 2) * 68 + r] = av.z; As[(kk + 3) * 68 + r] = av.w;
        Bs[(kk + 0) * 68 + r] = bv.x; Bs[(kk + 1) * 68 + r] = bv.y;
        Bs[(kk + 2) * 68 + r] = bv.z; Bs[(kk + 3) * 68 + r] = bv.w;
        __syncthreads();
#pragma unroll
        for (int k2 = 0; k2 < 16; k2++) {
            float4 a = *(float4*)&As[k2 * 68 + ty * 4];
            float4 b = *(float4*)&Bs[k2 * 68 + tx * 4];
            acc[0][0] += a.x * b.x; acc[0][1] += a.x * b.y; acc[0][2] += a.x * b.z; acc[0][3] += a.x * b.w;
            acc[1][0] += a.y * b.x; acc[1][1] += a.y * b.y; acc[1][2] += a.y * b.z; acc[1][3] += a.y * b.w;
            acc[2][0] += a.z * b.x; acc[2][1] += a.z * b.y; acc[2][2] += a.z * b.z; acc[2][3] += a.z * b.w;
            acc[3][0] += a.w * b.x; acc[3][1] += a.w * b.y; acc[3][2] += a.w * b.z; acc[3][3] += a.w * b.w;
        }
        __syncthreads();
    }

    float gg = ffg[0];
    float ee = ffe[0];
#pragma unroll
    for (int i = 0; i < 4; i++) {
        int row = rowTile + ty * 4 + i;
#pragma unroll
        for (int j = 0; j < 4; j++) {
            int col = jTile + tx * 4 + j;
            float vv = g_v[(size_t)row * Dsz + col];
            float za = ffa[col] * vv;
            float gel = 0.5f * za * (1.0f + erff(za * 0.70710678118654752f));
            float u = gg * gel + ee * sinf(ffb[col] * vv);
            atomicAdd(&out[(size_t)row * Dsz + col], u * acc[i][j]);
        }
    }
}

// ---------------------------------------------------------------------------
// ttt role: 2 rows/block, 4 warps/row, step PAIRS with M/A/G gram
// corrections. Triple-buffered pair slots; RACE-FREE publication:
// wait_prior -> __syncthreads -> stage next. Readouts via atomicAdd (RED).
// ---------------------------------------------------------------------------
__device__ __forceinline__ void stage_pair(int ps, float* dst, int tid) {
    const float* gt = g_train + (size_t)(2 * ps) * (Bsz * Dsz);
    const float* gs = g_state + (size_t)(2 * ps) * (Bsz * Dsz);
#pragma unroll
    for (int i = 0; i < 4; i++) {
        int idx4 = tid + i * 256;
        int b  = idx4 >> 6;
        int kc = (idx4 & 63) << 2;
        int off = b * TSTR + kc;
        __pipeline_memcpy_async(&dst[0 * TSZ + off], &gt[idx4 * 4], 16);
        __pipeline_memcpy_async(&dst[1 * TSZ + off], &gs[idx4 * 4], 16);
        __pipeline_memcpy_async(&dst[2 * TSZ + off], &gt[Bsz * Dsz + idx4 * 4], 16);
        __pipeline_memcpy_async(&dst[3 * TSZ + off], &gs[Bsz * Dsz + idx4 * 4], 16);
    }
    __pipeline_commit();
}

__device__ void ttt_role(float* smem, int blk,
                         const float* __restrict__ Wt, float* __restrict__ out) {
    float* sm_buf   = smem;                       // [3][4*TSZ]
    float* sm_cross = smem + 3 * 4 * TSZ;         // [8 warps][2][32]

    int tid  = threadIdx.x;
    int warp = tid >> 5;
    int lane = tid & 31;
    int r = warp >> 2;             // row within block (0,1)
    int p = warp & 3;              // k-part
    int d1 = blk * 2 + r;          // W row
    int k0 = p * 64 + 2 * lane;

    float2 wv = *(const float2*)&Wt[d1 * Dsz + k0];

    bool rdout = (p == 0 && lane >= 16);
    int  ob    = lane - 16;
    bool loA   = (lane < 16);

    stage_pair(0, sm_buf, tid);
    stage_pair(1, sm_buf + 4 * TSZ, tid);

    for (int ps = 0; ps < NP; ps++) {
        float* buf = sm_buf + (ps % 3) * (4 * TSZ);
        float* trs = buf;
        float* sts = buf + TSZ;
        float* tr1 = buf + 2 * TSZ;
        float* st1 = buf + 3 * TSZ;
        int s = 2 * ps;

        // ---- off-chain gmem prefetches ----
        float4 A0, A1, A2, A3;
        if (loA) {
            const float4* Ar = (const float4*)(g_A + ((size_t)ps * Bsz + lane) * Bsz);
            A0 = Ar[0]; A1 = Ar[1]; A2 = Ar[2]; A3 = Ar[3];
        }
        float4 m0, m1, m2, m3, n0, n1, n2, n3, G0, G1, G2, G3;
        float* op0 = 0; float* op1 = 0;
        if (rdout) {
            const float4* Mr = (const float4*)(g_M + ((size_t)s * Bsz + ob) * Bsz);
            m0 = Mr[0]; m1 = Mr[1]; m2 = Mr[2]; m3 = Mr[3];
            const float4* Nr = (const float4*)(g_M + ((size_t)(s + 1) * Bsz + ob) * Bsz);
            n0 = Nr[0]; n1 = Nr[1]; n2 = Nr[2]; n3 = Nr[3];
            const float4* Gr = (const float4*)(g_G + ((size_t)ps * Bsz + ob) * Bsz);
            G0 = Gr[0]; G1 = Gr[1]; G2 = Gr[2]; G3 = Gr[3];
            op0 = out + ((size_t)ob * Ssz + s) * Dsz + d1;
            op1 = op0 + Dsz;
        }

        // ---- confirm pair ps landed (own thread), then PUBLISH, then stage ----
        if (ps + 1 < NP) { __pipeline_wait_prior(1); }
        else             { __pipeline_wait_prior(0); }
        __syncthreads();   // publication barrier; also: pair ps-1 readers done
        if (ps + 2 < NP)
            stage_pair(ps + 2, sm_buf + ((ps + 2) % 3) * (4 * TSZ), tid);

        // ---- phase 1: partial dots for BOTH steps against w0 ----
        float a[32], c[32];
        float2 tc0[16], tc1[16];
#pragma unroll
        for (int b = 0; b < 16; b++) {
            float2 t0 = *(const float2*)&trs[b * TSTR + k0];
            float2 s0 = *(const float2*)&sts[b * TSTR + k0];
            float2 t1 = *(const float2*)&tr1[b * TSTR + k0];
            float2 s1 = *(const float2*)&st1[b * TSTR + k0];
            tc0[b] = t0;
            tc1[b] = t1;
            a[b]      = t0.x * wv.x + t0.y * wv.y;   // p1 partial
            a[16 + b] = s0.x * wv.x + s0.y * wv.y;   // q1 partial
            c[b]      = t1.x * wv.x + t1.y * wv.y;   // p2_0 partial
            c[16 + b] = s1.x * wv.x + s1.y * wv.y;   // q2_0 partial
        }
        float stc0 = 0.f, stc1 = 0.f;
        if (loA) {
            stc0 = sts[lane * TSTR + d1];
            stc1 = st1[lane * TSTR + d1];
        }

        // ---- interleaved register butterfly ----
#pragma unroll
        for (int m = 16; m >= 1; m >>= 1) {
            bool up = (lane & m) != 0;
#pragma unroll
            for (int j = 0; j < m; j++) {
                float ka = up ? a[j + m] : a[j];
                float ga = up ? a[j]     : a[j + m];
                a[j] = ka + __shfl_xor_sync(0xffffffffu, ga, m);
                float kc = up ? c[j + m] : c[j];
                float gc = up ? c[j]     : c[j + m];
                c[j] = kc + __shfl_xor_sync(0xffffffffu, gc, m);
            }
        }

        // ---- cross-warp combine ----
        sm_cross[(warp * 2 + 0) * 32 + lane] = a[0];
        sm_cross[(warp * 2 + 1) * 32 + lane] = c[0];
        __syncthreads();

        int rb = r * 4;
        float tot_a = (sm_cross[((rb + 0) * 2) * 32 + lane]
                     + sm_cross[((rb + 1) * 2) * 32 + lane])
                    + (sm_cross[((rb + 2) * 2) * 32 + lane]
                     + sm_cross[((rb + 3) * 2) * 32 + lane]);
        float tot_c = (sm_cross[((rb + 0) * 2 + 1) * 32 + lane]
                     + sm_cross[((rb + 1) * 2 + 1) * 32 + lane])
                    + (sm_cross[((rb + 2) * 2 + 1) * 32 + lane]
                     + sm_cross[((rb + 3) * 2 + 1) * 32 + lane]);

        // ---- step s: dif1 on lanes<16 ----
        float dv1 = loA ? (tot_a - stc0) : 0.f;
        float dif1[16];
#pragma unroll
        for (int j = 0; j < 16; j++) dif1[j] = __shfl_sync(0xffffffffu, dv1, j);

        // ---- step s+1: correct p2 with A·dif1, form dif2 ----
        float dv2 = 0.f;
        if (loA) {
            float cAh = A0.x * dif1[0]  + A0.y * dif1[1]  + A0.z * dif1[2]  + A0.w * dif1[3]
                      + A1.x * dif1[4]  + A1.y * dif1[5]  + A1.z * dif1[6]  + A1.w * dif1[7];
            float cAl = A2.x * dif1[8]  + A2.y * dif1[9]  + A2.z * dif1[10] + A2.w * dif1[11]
                      + A3.x * dif1[12] + A3.y * dif1[13] + A3.z * dif1[14] + A3.w * dif1[15];
            dv2 = (tot_c - LAM * (cAh + cAl)) - stc1;
        }
        float dif2[16];
#pragma unroll
        for (int j = 0; j < 16; j++) dif2[j] = __shfl_sync(0xffffffffu, dv2, j);

        // ---- w update FIRST (feeds next iteration), split accumulators ----
        float dwx0 = 0.f, dwx1 = 0.f, dwy0 = 0.f, dwy1 = 0.f;
#pragma unroll
        for (int b = 0; b < 16; b += 2) {
            dwx0 += dif1[b]     * tc0[b].x     + dif2[b]     * tc1[b].x;
            dwy0 += dif1[b]     * tc0[b].y     + dif2[b]     * tc1[b].y;
            dwx1 += dif1[b + 1] * tc0[b + 1].x + dif2[b + 1] * tc1[b + 1].x;
            dwy1 += dif1[b + 1] * tc0[b + 1].y + dif2[b + 1] * tc1[b + 1].y;
        }
        wv.x -= LAM * (dwx0 + dwx1);
        wv.y -= LAM * (dwy0 + dwy1);

        // ---- readouts (dead-end work, RED atomics, off the chain) ----
        if (rdout) {
            float ch = m0.x * dif1[0]  + m0.y * dif1[1]  + m0.z * dif1[2]  + m0.w * dif1[3]
                     + m1.x * dif1[4]  + m1.y * dif1[5]  + m1.z * dif1[6]  + m1.w * dif1[7];
            float cl = m2.x * dif1[8]  + m2.y * dif1[9]  + m2.z * dif1[10] + m2.w * dif1[11]
                     + m3.x * dif1[12] + m3.y * dif1[13] + m3.z * dif1[14] + m3.w * dif1[15];
            atomicAdd(op0, tot_a - LAM * (ch + cl));

            float gh = G0.x * dif1[0]  + G0.y * dif1[1]  + G0.z * dif1[2]  + G0.w * dif1[3]
                     + G1.x * dif1[4]  + G1.y * dif1[5]  + G1.z * dif1[6]  + G1.w * dif1[7];
            float gl = G2.x * dif1[8]  + G2.y * dif1[9]  + G2.z * dif1[10] + G2.w * dif1[11]
                     + G3.x * dif1[12] + G3.y * dif1[13] + G3.z * dif1[14] + G3.w * dif1[15];
            float q2 = tot_c - LAM * (gh + gl);
            float nh = n0.x * dif2[0]  + n0.y * dif2[1]  + n0.z * dif2[2]  + n0.w * dif2[3]
                     + n1.x * dif2[4]  + n1.y * dif2[5]  + n1.z * dif2[6]  + n1.w * dif2[7];
            float nl = n2.x * dif2[8]  + n2.y * dif2[9]  + n2.z * dif2[10] + n2.w * dif2[11]
                     + n3.x * dif2[12] + n3.y * dif2[13] + n3.z * dif2[14] + n3.w * dif2[15];
            atomicAdd(op1, q2 - LAM * (nh + nl));
        }
    }
}

// ---------------------------------------------------------------------------
// mega: bids 0..127 = ttt rows (occupy 128 SMs, wave 1);
//       bids 128..2175 = ff tiles (drain on the ~20 leftover SMs, hidden)
// ---------------------------------------------------------------------------
__global__ void __launch_bounds__(256, 1) mega_kernel(
    const float* __restrict__ Wt, const float* __restrict__ Wp,
    const float* __restrict__ ffa, const float* __restrict__ ffb,
    const float* __restrict__ ffg, const float* __restrict__ ffe,
    float* __restrict__ out) {
    extern __shared__ float smem[];
    if (blockIdx.x < NTTT) {
        ttt_role(smem, blockIdx.x, Wt, out);
    } else {
        ff_role(smem, blockIdx.x - NTTT, Wp, ffa, ffb, ffg, ffe, out);
    }
}

// ---------------------------------------------------------------------------
extern "C" void kernel_launch(void* const* d_in, const int* in_sizes, int n_in,
                              void* d_out, int out_size) {
    const float* x     = (const float*)d_in[0];
    const float* noise = (const float*)d_in[1];
    const float* a1    = (const float*)d_in[2];
    const float* a2    = (const float*)d_in[3];
    const float* Wt    = (const float*)d_in[4];
    const float* Wp    = (const float*)d_in[5];
    const float* ffa   = (const float*)d_in[6];
    const float* ffb   = (const float*)d_in[7];
    const float* ffg   = (const float*)d_in[8];
    const float* ffe   = (const float*)d_in[9];
    float* out = (float*)d_out;

    cudaMemsetAsync(out, 0, (size_t)out_size * sizeof(float));

    prep_kernel<<<(Bsz * Ssz * Dsz / 4) / 256, 256>>>(x, noise, a1, a2);

    const int PREP_SMEM = 4 * TSZ * (int)sizeof(float);               // ~66.6 KB
    cudaFuncSetAttribute(prep_pair_kernel, cudaFuncAttributeMaxDynamicSharedMemorySize, PREP_SMEM);
    prep_pair_kernel<<<NP, 256, PREP_SMEM>>>();

    const int MEGA_SMEM = (3 * 4 * TSZ + 512) * (int)sizeof(float);   // ~201.6 KB
    cudaFuncSetAttribute(mega_kernel, cudaFuncAttributeMaxDynamicSharedMemorySize, MEGA_SMEM);
    mega_kernel<<<NTTT + NFFX * NFFY, 256, MEGA_SMEM>>>(Wt, Wp, ffa, ffb, ffg, ffe, out);
}